// round 17
// baseline (speedup 1.0000x reference)
#include <cuda_runtime.h>
#include <cuda_fp16.h>
#include <cstdint>

#define NN 100000
#define DD 256
#define NE 3200000

// ---------------------------------------------------------------------------
// Device scratch (allocation-free rule: __device__ globals)
// ---------------------------------------------------------------------------
__device__ __half g_support[(size_t)NN * DD];  // x @ W, fp16 (halves gather bytes)
__device__ int    g_count[NN];                 // per-row edge count
__device__ int2   g_seg[NN];                   // per-row segment (start, end)
__device__ int    g_pos[NN];                   // scatter cursors
__device__ int2   g_edge[NE];                  // binned edges: (col, val bits)
__device__ int    g_total;                     // segment allocator cursor

// ---------------------------------------------------------------------------
// tf32 tensor-core GEMM (proven best: R14 fp16 m16n8k16 regressed — this
// GEMM is load-bound, not mma-issue-bound).
// ---------------------------------------------------------------------------
#define AS_STRIDE 36
#define BS_STRIDE 132

__device__ __forceinline__ unsigned f2tf(float f) {
    unsigned r;
    asm("cvt.rna.tf32.f32 %0, %1;" : "=r"(r) : "f"(f));
    return r;
}

__global__ void __launch_bounds__(256, 2) gemm_tc_kernel(const float* __restrict__ A,
                                                         const float* __restrict__ B) {
    __shared__ unsigned As[128 * AS_STRIDE];   // [m][k] tf32 bits
    __shared__ unsigned Bs[32 * BS_STRIDE];    // [k][n] tf32 bits

    const int tid  = threadIdx.x;
    const int warp = tid >> 5;
    const int lane = tid & 31;
    const int g    = lane >> 2;
    const int l    = lane & 3;

    const int wm = warp & 1;
    const int wn = warp >> 1;

    const int row0 = blockIdx.y * 128;
    const int col0 = blockIdx.x * 128;

    float c[4][4][4];
#pragma unroll
    for (int i = 0; i < 4; i++)
#pragma unroll
        for (int j = 0; j < 4; j++)
#pragma unroll
            for (int q = 0; q < 4; q++) c[i][j][q] = 0.0f;

    for (int k0 = 0; k0 < DD; k0 += 32) {
#pragma unroll
        for (int i = 0; i < 4; i++) {
            const int rl = warp * 16 + i * 4 + (lane >> 3);
            int gr = row0 + rl;
            gr = gr < NN ? gr : NN - 1;
            const int f4 = (lane & 7) * 4;
            float4 v = *(const float4*)(A + (size_t)gr * DD + k0 + f4);
            unsigned* d = &As[rl * AS_STRIDE + f4];
            d[0] = f2tf(v.x); d[1] = f2tf(v.y); d[2] = f2tf(v.z); d[3] = f2tf(v.w);
        }
#pragma unroll
        for (int i = 0; i < 4; i++) {
            const int kl = warp * 4 + i;
            float4 v = *(const float4*)(B + (size_t)(k0 + kl) * DD + col0 + lane * 4);
            unsigned* d = &Bs[kl * BS_STRIDE + lane * 4];
            d[0] = f2tf(v.x); d[1] = f2tf(v.y); d[2] = f2tf(v.z); d[3] = f2tf(v.w);
        }
        __syncthreads();

#pragma unroll
        for (int kk = 0; kk < 32; kk += 8) {
            unsigned af[4][4];
#pragma unroll
            for (int i = 0; i < 4; i++) {
                const int mr = wm * 64 + i * 16 + g;
                af[i][0] = As[(mr)     * AS_STRIDE + kk + l];
                af[i][1] = As[(mr + 8) * AS_STRIDE + kk + l];
                af[i][2] = As[(mr)     * AS_STRIDE + kk + l + 4];
                af[i][3] = As[(mr + 8) * AS_STRIDE + kk + l + 4];
            }
            unsigned bf[4][2];
#pragma unroll
            for (int j = 0; j < 4; j++) {
                const int nc = wn * 32 + j * 8 + g;
                bf[j][0] = Bs[(kk + l)     * BS_STRIDE + nc];
                bf[j][1] = Bs[(kk + l + 4) * BS_STRIDE + nc];
            }
#pragma unroll
            for (int i = 0; i < 4; i++)
#pragma unroll
                for (int j = 0; j < 4; j++) {
                    asm volatile(
                        "mma.sync.aligned.m16n8k8.row.col.f32.tf32.tf32.f32 "
                        "{%0,%1,%2,%3}, {%4,%5,%6,%7}, {%8,%9}, {%0,%1,%2,%3};"
                        : "+f"(c[i][j][0]), "+f"(c[i][j][1]),
                          "+f"(c[i][j][2]), "+f"(c[i][j][3])
                        : "r"(af[i][0]), "r"(af[i][1]), "r"(af[i][2]), "r"(af[i][3]),
                          "r"(bf[j][0]), "r"(bf[j][1]));
                }
        }
        __syncthreads();
    }

#pragma unroll
    for (int i = 0; i < 4; i++) {
        const int r_lo = row0 + wm * 64 + i * 16 + g;
        const int r_hi = r_lo + 8;
#pragma unroll
        for (int j = 0; j < 4; j++) {
            const int cc = col0 + wn * 32 + j * 8 + 2 * l;
            if (r_lo < NN)
                *(__half2*)(g_support + (size_t)r_lo * DD + cc) =
                    __floats2half2_rn(c[i][j][0], c[i][j][1]);
            if (r_hi < NN)
                *(__half2*)(g_support + (size_t)r_hi * DD + cc) =
                    __floats2half2_rn(c[i][j][2], c[i][j][3]);
        }
    }
}

// ---------------------------------------------------------------------------
// CSR build: histogram -> per-block segment allocation -> scatter.
// NO cross-block ordering needed: aggregate only requires each row's edges
// to be contiguous, so blocks claim segment space with one atomicAdd each.
// ---------------------------------------------------------------------------
__global__ void __launch_bounds__(256) zero_count_kernel() {
    int i = blockIdx.x * 256 + threadIdx.x;
    if (i < NN) g_count[i] = 0;
    if (i == 0) g_total = 0;
}

__global__ void __launch_bounds__(256) hist_kernel(const int* __restrict__ er, int E) {
    int e = blockIdx.x * 256 + threadIdx.x;
    if (e < E) atomicAdd(&g_count[er[e]], 1);
}

// Intra-block scan + one global atomicAdd per block. No inter-block waits.
__global__ void __launch_bounds__(256) alloc_kernel() {
    __shared__ int sh[256];
    __shared__ int sbase;
    const int t = threadIdx.x;
    const int i = blockIdx.x * 256 + t;

    const int c = (i < NN) ? g_count[i] : 0;
    sh[t] = c;
    __syncthreads();
#pragma unroll
    for (int off = 1; off < 256; off <<= 1) {
        int p = (t >= off) ? sh[t - off] : 0;
        __syncthreads();
        sh[t] += p;
        __syncthreads();
    }
    const int incl = sh[t];
    if (t == 255) sbase = atomicAdd(&g_total, incl);
    __syncthreads();

    if (i < NN) {
        const int s = sbase + incl - c;
        g_seg[i] = make_int2(s, s + c);
        g_pos[i] = s;
    }
}

__global__ void __launch_bounds__(256) scatter_kernel(const float* __restrict__ ev,
                                                      const int* __restrict__ er,
                                                      const int* __restrict__ ec,
                                                      int E) {
    int e = blockIdx.x * 256 + threadIdx.x;
    if (e < E) {
        int p = atomicAdd(&g_pos[er[e]], 1);
        g_edge[p] = make_int2(ec[e], __float_as_int(ev[e]));
    }
}

// ---------------------------------------------------------------------------
// Aggregate + ReLU: one warp per row, fp16 support gathers, fp32 accumulate.
// ---------------------------------------------------------------------------
__global__ void __launch_bounds__(256) aggregate_kernel(float* __restrict__ out) {
    const int row  = (blockIdx.x * 256 + threadIdx.x) >> 5;
    const int lane = threadIdx.x & 31;
    if (row >= NN) return;

    const int2 se = g_seg[row];
    const int s = se.x;
    const int e = se.y;

    float a[8];
#pragma unroll
    for (int q = 0; q < 8; q++) a[q] = 0.0f;

    for (int base = s; base < e; base += 32) {
        const int idx = base + lane;
        int2 ed = (idx < e) ? g_edge[idx] : make_int2(0, 0);
        const int n = min(32, e - base);
        for (int j = 0; j < n; j++) {
            const int   cc = __shfl_sync(0xffffffffu, ed.x, j);
            const float vv = __int_as_float(__shfl_sync(0xffffffffu, ed.y, j));
            const float4* sp = (const float4*)(g_support + (size_t)cc * DD);
            float4 raw = __ldg(sp + lane);
            const __half2* h = (const __half2*)&raw;
            float2 f0 = __half22float2(h[0]);
            float2 f1 = __half22float2(h[1]);
            float2 f2 = __half22float2(h[2]);
            float2 f3 = __half22float2(h[3]);
            a[0] += vv * f0.x; a[1] += vv * f0.y;
            a[2] += vv * f1.x; a[3] += vv * f1.y;
            a[4] += vv * f2.x; a[5] += vv * f2.y;
            a[6] += vv * f3.x; a[7] += vv * f3.y;
        }
    }

#pragma unroll
    for (int q = 0; q < 8; q++) a[q] = fmaxf(a[q], 0.0f);

    float4* o = (float4*)(out + (size_t)row * DD + lane * 8);
    o[0] = make_float4(a[0], a[1], a[2], a[3]);
    o[1] = make_float4(a[4], a[5], a[6], a[7]);
}

// ---------------------------------------------------------------------------
// Launch: serial, 6 kernels.
// ---------------------------------------------------------------------------
extern "C" void kernel_launch(void* const* d_in, const int* in_sizes, int n_in,
                              void* d_out, int out_size) {
    const float* x  = (const float*)d_in[0];
    const float* w  = (const float*)d_in[1];
    const float* ev = (const float*)d_in[2];
    const int*   er = (const int*)d_in[3];
    const int*   ec = (const int*)d_in[4];
    float*       out = (float*)d_out;
    const int E = in_sizes[2];

    const int gE = (E + 255) / 256;
    const int gN = (NN + 255) / 256;

    gemm_tc_kernel<<<dim3(DD / 128, (NN + 127) / 128), 256>>>(x, w);
    zero_count_kernel<<<gN, 256>>>();
    hist_kernel<<<gE, 256>>>(er, E);
    alloc_kernel<<<gN, 256>>>();
    scatter_kernel<<<gE, 256>>>(ev, er, ec, E);
    aggregate_kernel<<<(NN * 32 + 255) / 256, 256>>>(out);
}